// round 13
// baseline (speedup 1.0000x reference)
#include <cuda_runtime.h>

// RvNN fused kernel v9 (re-bench, byte-identical: prior round was a container
// failure with no kernel-attributable defect found on audit).
// v6 tf32 mma.sync design at 1024 threads/block (32 warps, occupancy 50%).

#define DEVINL __device__ __forceinline__
typedef unsigned int u32;
typedef unsigned long long u64;

constexpr int NTH = 1024;
constexpr int BB  = 16;

// prepacked B-fragment segments (float2 units): [ks][ntile][lane] = (b0,b1)
constexpr int OC2 = 0;       // Wc2: 16 ks x 32 nt x 32
constexpr int OP2 = 16384;   // Wp2
constexpr int OL1 = 32768;   // Wl1: 64 ks x 16 nt x 32
constexpr int NPAIR = 65536; // 512 KB
__device__ __align__(16) float2 g_packed[NPAIR];

// ---- smem layout (float offsets) ----
constexpr int STRU = 132;    // U/H row stride (conflict-free frag loads)
constexpr int STRC = 516;    // CHPA row stride
constexpr int SM_U    = 0;                 // 64*132 = 8448
constexpr int SM_CHPA = 8448;              // 64*516 = 33024 (X staging aliases)
constexpr int SM_WT   = 41472;             // 8192 floats (tiles: 2 x 2048 pairs; PART)
constexpr int SM_Y    = 49664;             // 768
constexpr int SM_S12  = 50432;             // 768
constexpr int SM_TOT  = 51200;             // 204800 bytes

DEVINL float sanf(float x) {
    if (isnan(x)) return 0.0f;
    if (isinf(x)) return 9999.0f;
    return x;
}

DEVINL float fast_tanh(float x) {
    float ax = fabsf(x) * 2.8853900817779268f;  // 2*log2(e)
    float e; asm("ex2.approx.f32 %0, %1;" : "=f"(e) : "f"(ax));
    float r; asm("rcp.approx.f32 %0, %1;" : "=f"(r) : "f"(e + 1.0f));
    float t = fmaf(-2.0f, r, 1.0f);
    return copysignf(t, x);
}

DEVINL float tf32f(float x) {
    u32 y; asm("cvt.rna.tf32.f32 %0, %1;" : "=r"(y) : "f"(x));
    return __uint_as_float(y);
}

DEVINL void mma8(float* d, const u32* a, u32 b0, u32 b1) {
    asm("mma.sync.aligned.m16n8k8.row.col.f32.tf32.tf32.f32 "
        "{%0,%1,%2,%3}, {%4,%5,%6,%7}, {%8,%9}, {%0,%1,%2,%3};"
        : "+f"(d[0]), "+f"(d[1]), "+f"(d[2]), "+f"(d[3])
        : "r"(a[0]), "r"(a[1]), "r"(a[2]), "r"(a[3]), "r"(b0), "r"(b1));
}

DEVINL void cpa16(void* dst, const void* src) {
    unsigned sa = (unsigned)__cvta_generic_to_shared(dst);
    asm volatile("cp.async.cg.shared.global [%0], [%1], 16;" :: "r"(sa), "l"(src));
}
DEVINL void cpa_commit() { asm volatile("cp.async.commit_group;"); }
DEVINL void cpa_wait0()  { asm volatile("cp.async.wait_group 0;"); }

// ---------- prepack: W[K][N] -> fragment pairs (tf32-rounded) ----------
__global__ void prepack_kernel(const float* __restrict__ Wc2,
                               const float* __restrict__ Wp2,
                               const float* __restrict__ Wl1)
{
    int idx = blockIdx.x * blockDim.x + threadIdx.x;
    if (idx >= NPAIR) return;
    const float* W; int p, N, ks, nt, lane;
    if (idx < OP2)      { W = Wc2; p = idx;       N = 256; ks = p >> 10; int rem = p & 1023; nt = rem >> 5; lane = rem & 31; }
    else if (idx < OL1) { W = Wp2; p = idx - OP2; N = 256; ks = p >> 10; int rem = p & 1023; nt = rem >> 5; lane = rem & 31; }
    else                { W = Wl1; p = idx - OL1; N = 128; ks = p >> 9;  int rem = p & 511;  nt = rem >> 5; lane = rem & 31; }
    int k0 = 8 * ks + (lane & 3);
    int n  = 8 * nt + (lane >> 2);
    float2 v;
    v.x = tf32f(W[k0 * N + n]);
    v.y = tf32f(W[(k0 + 4) * N + n]);
    g_packed[idx] = v;
}

// ---------- layer1: A[M][KA] @ W[KA][128] + b -> prelu -> U (stride STRU, tf32) ----------
// 32 warps: ty = warp (0..31), rows ty*RPT..; cols tx + 32j.
template<int M, int KA>
DEVINL void layer1(const float* __restrict__ A, const float* __restrict__ WT,
                   const float* __restrict__ bg, float alpha,
                   float* __restrict__ U, int tx, int ty)
{
    constexpr int RPT = M / 32;
    float acc[RPT][4];
#pragma unroll
    for (int r = 0; r < RPT; r++)
#pragma unroll
        for (int j = 0; j < 4; j++) acc[r][j] = 0.0f;

#pragma unroll
    for (int k = 0; k < KA; k += 4) {
        float a[RPT][4];
#pragma unroll
        for (int r = 0; r < RPT; r++) {
            float4 v = *(const float4*)&A[(ty * RPT + r) * KA + k];
            a[r][0] = v.x; a[r][1] = v.y; a[r][2] = v.z; a[r][3] = v.w;
        }
#pragma unroll
        for (int j4 = 0; j4 < 4; j4++) {
            float w[4];
#pragma unroll
            for (int j = 0; j < 4; j++) w[j] = WT[(k + j4) * 128 + tx + 32 * j];
#pragma unroll
            for (int r = 0; r < RPT; r++)
#pragma unroll
                for (int j = 0; j < 4; j++)
                    acc[r][j] = fmaf(a[r][j4], w[j], acc[r][j]);
        }
    }
#pragma unroll
    for (int r = 0; r < RPT; r++)
#pragma unroll
        for (int j = 0; j < 4; j++) {
            int c = tx + 32 * j;
            float v = acc[r][j] + bg[c];
            v = (v >= 0.0f) ? v : alpha * v;
            U[(ty * RPT + r) * STRU + c] = tf32f(v);
        }
}

// ---------- layer2 (mma): U[M][128] @ W[128][256] + b -> tanh -> CHPA[:, colOff..) ----------
// 32 warps: warp owns m-tile mi = w % MT and n8-tiles nb..nb+MT-1, nb = (w/MT)*MT.
template<int M>
DEVINL void layer2(const float* __restrict__ U, const float2* __restrict__ Pg,
                   const float* __restrict__ bg, float* __restrict__ CH, int colOff,
                   float* __restrict__ WTf, int tid)
{
    constexpr int MT = M / 16;   // tiles per warp (4 for M=64, 2 for M=32)
    const int w = tid >> 5, lane = tid & 31;
    const int mi = w % MT;
    const int nb = (w / MT) * MT;
    const int r = lane >> 2, cth = lane & 3;
    const u32* Uu = (const u32*)U;
    const int abase = (mi * 16 + r) * STRU + cth;

    float acc[MT][4];
#pragma unroll
    for (int j = 0; j < MT; j++)
#pragma unroll
        for (int q = 0; q < 4; q++) acc[j][q] = 0.0f;

    // preload tile 0 (2 ksteps = 2048 pairs = 16KB)
    for (int s = tid; s < 1024; s += NTH) cpa16((float2*)WTf + s * 2, Pg + s * 2);
    cpa_commit(); cpa_wait0();
    __syncthreads();

    for (int t = 0; t < 8; t++) {
        const u64* bt = (const u64*)((const float2*)WTf + (t & 1) * 2048);
        if (t + 1 < 8) {
            float2* nbuf = (float2*)WTf + ((t + 1) & 1) * 2048;
            const float2* ns = Pg + (t + 1) * 2048;
            for (int s = tid; s < 1024; s += NTH) cpa16(nbuf + s * 2, ns + s * 2);
            cpa_commit();
        }
#pragma unroll
        for (int kk = 0; kk < 2; kk++) {
            const int kA = (2 * t + kk) * 8;
            u32 a[4];
            a[0] = Uu[abase + kA];
            a[1] = Uu[abase + kA + 8 * STRU];
            a[2] = Uu[abase + kA + 4];
            a[3] = Uu[abase + kA + 8 * STRU + 4];
#pragma unroll
            for (int j = 0; j < MT; j++) {
                u64 b = bt[(kk * 32 + nb + j) * 32 + lane];
                mma8(acc[j], a, (u32)b, (u32)(b >> 32));
            }
        }
        cpa_wait0();
        __syncthreads();
    }
#pragma unroll
    for (int j = 0; j < MT; j++) {
        int row0 = mi * 16 + r;
        int c0 = colOff + (nb + j) * 8 + 2 * cth;
        float b0 = bg[(nb + j) * 8 + 2 * cth], b1 = bg[(nb + j) * 8 + 2 * cth + 1];
        float2 v0, v1;
        v0.x = tf32f(fast_tanh(acc[j][0] + b0));
        v0.y = tf32f(fast_tanh(acc[j][1] + b1));
        v1.x = tf32f(fast_tanh(acc[j][2] + b0));
        v1.y = tf32f(fast_tanh(acc[j][3] + b1));
        *(float2*)&CH[row0 * STRC + c0] = v0;
        *(float2*)&CH[(row0 + 8) * STRC + c0] = v1;
    }
}

// ---------- layer3 (mma, split-K 2): CHPA[M][512] @ Wl1[512][128] + b -> tanh -> H ----------
// groups of 16 warps; within group warp owns mi = wl % MT, n8-tiles nb..nb+MT-1.
template<int M>
DEVINL void layer3(const float* __restrict__ CP, const float2* __restrict__ Pg,
                   const float* __restrict__ bl1, float* __restrict__ H,
                   float* __restrict__ WTf, int tid)
{
    constexpr int MT = M / 16;
    const int w = tid >> 5, lane = tid & 31;
    const int kg = w >> 4, wl = w & 15;
    const int mi = wl % MT;
    const int nb = (wl / MT) * MT;
    const int r = lane >> 2, cth = lane & 3;
    const u32* Cu = (const u32*)CP;
    const int abase = (mi * 16 + r) * STRC + cth;

    float acc[MT][4];
#pragma unroll
    for (int j = 0; j < MT; j++)
#pragma unroll
        for (int q = 0; q < 4; q++) acc[j][q] = 0.0f;

    // tile t: g0 ks{2t,2t+1} at pairs [0,1024), g1 ks{32+2t,32+2t+1} at [1024,2048)
    {
        for (int s = tid; s < 1024; s += NTH) {
            int half = s >> 9, off = s & 511;
            const float2* src = Pg + (half ? 32 : 0) * 512 + off * 2;
            cpa16((float2*)WTf + s * 2, src);
        }
        cpa_commit(); cpa_wait0();
        __syncthreads();
    }
    for (int t = 0; t < 16; t++) {
        const u64* bt = (const u64*)((const float2*)WTf + (t & 1) * 2048);
        if (t + 1 < 16) {
            float2* nbuf = (float2*)WTf + ((t + 1) & 1) * 2048;
            for (int s = tid; s < 1024; s += NTH) {
                int half = s >> 9, off = s & 511;
                const float2* src = Pg + (half ? (32 + 2 * (t + 1)) : (2 * (t + 1))) * 512 + off * 2;
                cpa16(nbuf + s * 2, src);
            }
            cpa_commit();
        }
#pragma unroll
        for (int kk = 0; kk < 2; kk++) {
            const int kA = (kg * 32 + 2 * t + kk) * 8;
            u32 a[4];
            a[0] = Cu[abase + kA];
            a[1] = Cu[abase + kA + 8 * STRC];
            a[2] = Cu[abase + kA + 4];
            a[3] = Cu[abase + kA + 8 * STRC + 4];
#pragma unroll
            for (int j = 0; j < MT; j++) {
                u64 b = bt[((kg * 2 + kk) * 16 + nb + j) * 32 + lane];
                mma8(acc[j], a, (u32)b, (u32)(b >> 32));
            }
        }
        cpa_wait0();
        __syncthreads();
    }
    // reduce split-K partials via PART (aliases WT, stride 128)
    float* PART = WTf;
    if (kg == 1) {
#pragma unroll
        for (int j = 0; j < MT; j++) {
            int row0 = mi * 16 + r;
            int c0 = (nb + j) * 8 + 2 * cth;
            float2 v0 = { acc[j][0], acc[j][1] };
            float2 v1 = { acc[j][2], acc[j][3] };
            *(float2*)&PART[row0 * 128 + c0] = v0;
            *(float2*)&PART[(row0 + 8) * 128 + c0] = v1;
        }
    }
    __syncthreads();
    if (kg == 0) {
#pragma unroll
        for (int j = 0; j < MT; j++) {
            int row0 = mi * 16 + r;
            int c0 = (nb + j) * 8 + 2 * cth;
            float2 p0 = *(const float2*)&PART[row0 * 128 + c0];
            float2 p1 = *(const float2*)&PART[(row0 + 8) * 128 + c0];
            float b0 = bl1[c0], b1 = bl1[c0 + 1];
            H[row0 * STRU + c0]           = fast_tanh(acc[j][0] + p0.x + b0);
            H[row0 * STRU + c0 + 1]       = fast_tanh(acc[j][1] + p0.y + b1);
            H[(row0 + 8) * STRU + c0]     = fast_tanh(acc[j][2] + p1.x + b0);
            H[(row0 + 8) * STRU + c0 + 1] = fast_tanh(acc[j][3] + p1.y + b1);
        }
    }
}

// ---------- layer4: H[M][128] @ Wl2[128][32] + b -> prelu -> S12 / out ----------
template<int M, bool FINAL>
DEVINL void layer4(const float* __restrict__ H, const float* __restrict__ WT,
                   const float* __restrict__ bl2, float al,
                   float* __restrict__ S12, float* __restrict__ out,
                   int b0, int nb, int tx, int ty)
{
    constexpr int RPT = M / 32;
    float acc[RPT];
#pragma unroll
    for (int r = 0; r < RPT; r++) acc[r] = 0.0f;
#pragma unroll
    for (int k = 0; k < 128; k += 4) {
        float a[RPT][4];
#pragma unroll
        for (int r = 0; r < RPT; r++) {
            float4 v = *(const float4*)&H[(ty * RPT + r) * STRU + k];
            a[r][0] = v.x; a[r][1] = v.y; a[r][2] = v.z; a[r][3] = v.w;
        }
#pragma unroll
        for (int j = 0; j < 4; j++) {
            float wv = WT[(k + j) * 32 + tx];
#pragma unroll
            for (int r = 0; r < RPT; r++) acc[r] = fmaf(a[r][j], wv, acc[r]);
        }
    }
#pragma unroll
    for (int r = 0; r < RPT; r++) {
        float v = acc[r] + bl2[tx];
        v = (v >= 0.0f) ? v : al * v;
        int row = ty * RPT + r;
        if (FINAL) {
            int be = b0 + (row >> 1);
            if (be < nb) out[(size_t)be * 64 + (row & 1) * 32 + tx] = v;
        } else {
            if (tx < 12) S12[row * 12 + tx] = v;
        }
    }
}

// ---------- full combine() pipeline for M rows ----------
template<int M, bool FINAL>
DEVINL void pipeline(float* sm, int tid,
                     const float* Wc1, const float* bc1, float ac,
                     const float* bc2,
                     const float* Wp1, const float* bp1, float ap,
                     const float* bp2,
                     const float* bl1,
                     const float* Wl2, const float* bl2, float al,
                     float* out, int b0, int nb)
{
    float* U    = sm + SM_U;      // also H (alias)
    float* CHPA = sm + SM_CHPA;
    float* WT   = sm + SM_WT;
    float* X    = sm + SM_CHPA;   // alias (consumed before CHPA written)
    float* Y    = sm + SM_Y;
    float* S12  = sm + SM_S12;
    const int tx = tid & 31, ty = tid >> 5;
    const float2* gP = g_packed;

    // A1: U = prelu(X @ Wc1 + bc1)
    for (int i = tid; i < 24 * 128; i += NTH) WT[i] = Wc1[i];
    __syncthreads();
    layer1<M, 24>(X, WT, bc1, ac, U, tx, ty);
    __syncthreads();
    // B1: ch -> CHPA cols [0,256)
    layer2<M>(U, gP + OC2, bc2, CHPA, 0, WT, tid);
    __syncthreads();
    // A2: V = prelu(Y @ Wp1 + bp1) (overwrites U)
    for (int i = tid; i < 12 * 128; i += NTH) WT[i] = Wp1[i];
    __syncthreads();
    layer1<M, 12>(Y, WT, bp1, ap, U, tx, ty);
    __syncthreads();
    // B2: pa -> CHPA cols [256,512)
    layer2<M>(U, gP + OP2, bp2, CHPA, 256, WT, tid);
    __syncthreads();
    // C: h = tanh(CHPA @ Wl1 + bl1) -> H (aliases U)
    layer3<M>(CHPA, gP + OL1, bl1, U, WT, tid);
    __syncthreads();
    // D: out = prelu(h @ Wl2 + bl2)
    for (int i = tid; i < 128 * 32; i += NTH) WT[i] = Wl2[i];
    __syncthreads();
    layer4<M, FINAL>(U, WT, bl2, al, S12, out, b0, nb, tx, ty);
}

__global__ void __launch_bounds__(NTH, 1)
rvnn_kernel(const float* __restrict__ level1, const float* __restrict__ level2,
            const float* __restrict__ level3,
            const float* __restrict__ Wc1, const float* __restrict__ bc1, const float* __restrict__ ac,
            const float* __restrict__ bc2,
            const float* __restrict__ Wp1, const float* __restrict__ bp1, const float* __restrict__ ap,
            const float* __restrict__ bp2,
            const float* __restrict__ bl1,
            const float* __restrict__ Wl2, const float* __restrict__ bl2, const float* __restrict__ al,
            float* __restrict__ out, int nb)
{
    extern __shared__ float sm[];
    const int tid = threadIdx.x;
    const int b0 = blockIdx.x * BB;
    const float acv = *ac, apv = *ap, alv = *al;

    float* X   = sm + SM_CHPA;
    float* Y   = sm + SM_Y;
    float* S12 = sm + SM_S12;

    // ---- stage 1 input staging (rows = BB*4 = 64) ----
    {
        const float* src = level3 + (size_t)b0 * 96;
        int lim = (nb - b0 < BB ? nb - b0 : BB) * 96;
        for (int i = tid; i < BB * 96; i += NTH) {
            float v = (i < lim) ? sanf(src[i]) : 0.0f;
            int be = i / 96, rem = i % 96, c = rem / 12, k = rem % 12;
            int p = c >> 1, s = c & 1;
            X[(be * 4 + p) * 24 + (1 - s) * 12 + k] = v;
        }
    }
    {
        const float* src = level2 + (size_t)b0 * 48;
        int lim = (nb - b0 < BB ? nb - b0 : BB) * 48;
        for (int i = tid; i < BB * 48; i += NTH) {
            float v = (i < lim) ? sanf(src[i]) : 0.0f;
            int be = i / 48, rem = i % 48, p = rem / 12, k = rem % 12;
            Y[(be * 4 + p) * 12 + k] = v;
        }
    }
    __syncthreads();

    pipeline<64, false>(sm, tid, Wc1, bc1, acv, bc2, Wp1, bp1, apv,
                        bp2, bl1, Wl2, bl2, alv, out, b0, nb);
    __syncthreads();

    // ---- stage 2 input staging (rows = BB*2 = 32) ----
    for (int i = tid; i < 32 * 24; i += NTH) {
        int r2 = i / 24, k24 = i % 24, be = r2 >> 1, p = r2 & 1;
        int j = 2 * p + (k24 < 12 ? 1 : 0);
        int k = (k24 < 12) ? k24 : (k24 - 12);
        X[r2 * 24 + k24] = sanf(S12[(be * 4 + j) * 12 + k]);
    }
    {
        const float* src = level1 + (size_t)b0 * 24;
        int lim = (nb - b0 < BB ? nb - b0 : BB) * 24;
        for (int i = tid; i < BB * 24; i += NTH) {
            float v = (i < lim) ? sanf(src[i]) : 0.0f;
            int be = i / 24, rem = i % 24, p = rem / 12, k = rem % 12;
            Y[(be * 2 + p) * 12 + k] = v;
        }
    }
    __syncthreads();

    pipeline<32, true>(sm, tid, Wc1, bc1, acv, bc2, Wp1, bp1, apv,
                       bp2, bl1, Wl2, bl2, alv, out, b0, nb);
}

extern "C" void kernel_launch(void* const* d_in, const int* in_sizes, int n_in,
                              void* d_out, int out_size) {
    const float* level1 = (const float*)d_in[0];
    const float* level2 = (const float*)d_in[1];
    const float* level3 = (const float*)d_in[2];
    const float* Wc1 = (const float*)d_in[3];
    const float* bc1 = (const float*)d_in[4];
    const float* ac  = (const float*)d_in[5];
    const float* Wc2 = (const float*)d_in[6];
    const float* bc2 = (const float*)d_in[7];
    const float* Wp1 = (const float*)d_in[8];
    const float* bp1 = (const float*)d_in[9];
    const float* ap  = (const float*)d_in[10];
    const float* Wp2 = (const float*)d_in[11];
    const float* bp2 = (const float*)d_in[12];
    const float* Wl1 = (const float*)d_in[13];
    const float* bl1 = (const float*)d_in[14];
    const float* Wl2 = (const float*)d_in[15];
    const float* bl2 = (const float*)d_in[16];
    const float* al  = (const float*)d_in[17];
    float* out = (float*)d_out;

    int nb = in_sizes[0] / 24;
    int grid = (nb + BB - 1) / BB;
    size_t smem = (size_t)SM_TOT * sizeof(float);  // 204800 B

    prepack_kernel<<<(NPAIR + 255) / 256, 256>>>(Wc2, Wp2, Wl1);

    cudaFuncSetAttribute(rvnn_kernel, cudaFuncAttributeMaxDynamicSharedMemorySize, (int)smem);
    rvnn_kernel<<<grid, NTH, smem>>>(level1, level2, level3, Wc1, bc1, ac, bc2,
                                     Wp1, bp1, ap, bp2, bl1, Wl2, bl2, al,
                                     out, nb);
}

// round 14
// speedup vs baseline: 1.8370x; 1.8370x over previous
#include <cuda_runtime.h>

// RvNN fused kernel v10: fp16 mma.sync m16n8k16 (same 10-bit mantissa as tf32,
// half the LDS bytes + half the mma count). Whole-layer fragment images resident
// in one 64KB smem buffer; ~12 barriers per pipeline; v6-style 2m x 4n reuse tiling.

#define DEVINL __device__ __forceinline__
typedef unsigned int u32;
typedef unsigned long long u64;

constexpr int NTH = 512;
constexpr int BB  = 16;

// prepacked fp16 B-fragment images (u64 per (kstep16, n8tile, lane)):
constexpr int OC2 = 0;       // Wc2: 8 ks x 32 nt x 32
constexpr int OP2 = 8192;    // Wp2: 8 ks x 32 nt x 32
constexpr int OL1 = 16384;   // Wl1: 32 ks x 16 nt x 32
constexpr int NP  = 32768;   // 256 KB
__device__ __align__(16) u64 g_packed[NP];

// ---- smem layout (float offsets) ----
constexpr int SU = 68;       // u32 row stride of U (136 fp16)
constexpr int SC = 260;      // u32 row stride of CHPA (520 fp16)
constexpr int SH = 132;      // f32 row stride of H
constexpr int SM_U    = 0;       // 4352 floats (u32 view: 64 x 68)
constexpr int SM_CHPA = 4352;    // 16640 floats (u32 view: 64 x 260)
constexpr int SM_H    = 20992;   // 8448 floats (X staging aliases head)
constexpr int SM_WT   = 29440;   // 16384 floats = 8192 u64 (64 KB)
constexpr int SM_WS   = 45824;   // 4096 floats (Wc1/Wp1/Wl2 fp32)
constexpr int SM_Y    = 49920;   // 768
constexpr int SM_S12  = 50688;   // 768
constexpr int SM_TOT  = 51456;   // 205824 bytes

DEVINL float sanf(float x) {
    if (isnan(x)) return 0.0f;
    if (isinf(x)) return 9999.0f;
    return x;
}
DEVINL float fast_tanh(float x) {
    float ax = fabsf(x) * 2.8853900817779268f;  // 2*log2(e)
    float e; asm("ex2.approx.f32 %0, %1;" : "=f"(e) : "f"(ax));
    float r; asm("rcp.approx.f32 %0, %1;" : "=f"(r) : "f"(e + 1.0f));
    float t = fmaf(-2.0f, r, 1.0f);
    return copysignf(t, x);
}
// pack (lo, hi) floats -> fp16x2 in u32  (cvt.rn.f16x2.f32 d, hi, lo)
DEVINL u32 pkh2(float lo, float hi) {
    u32 r; asm("cvt.rn.f16x2.f32 %0, %1, %2;" : "=r"(r) : "f"(hi), "f"(lo)); return r;
}
DEVINL void mma16(float* d, const u32* a, u32 b0, u32 b1) {
    asm("mma.sync.aligned.m16n8k16.row.col.f32.f16.f16.f32 "
        "{%0,%1,%2,%3}, {%4,%5,%6,%7}, {%8,%9}, {%0,%1,%2,%3};"
        : "+f"(d[0]), "+f"(d[1]), "+f"(d[2]), "+f"(d[3])
        : "r"(a[0]), "r"(a[1]), "r"(a[2]), "r"(a[3]), "r"(b0), "r"(b1));
}
DEVINL void cpa16(void* dst, const void* src) {
    unsigned sa = (unsigned)__cvta_generic_to_shared(dst);
    asm volatile("cp.async.cg.shared.global [%0], [%1], 16;" :: "r"(sa), "l"(src));
}
DEVINL void cpa_commit() { asm volatile("cp.async.commit_group;"); }
DEVINL void cpa_wait0()  { asm volatile("cp.async.wait_group 0;"); }
DEVINL void cpa_wait1()  { asm volatile("cp.async.wait_group 1;"); }

DEVINL void load_ws(float* WS, const float* src, int nfloats, int tid) {
    for (int s = tid; s < nfloats / 4; s += NTH) cpa16(WS + s * 4, src + s * 4);
}
DEVINL void load_wt(float* WT, const u64* src, int tid) {   // 8192 u64 = 64KB
    u64* d = (u64*)WT;
    for (int s = tid; s < 4096; s += NTH) cpa16(d + s * 2, src + s * 2);
}

// ---------- prepack: W[K][N] fp32 -> fp16 fragment u64 per (ks16, nt, lane) ----------
// b0 = {W[k0][n], W[k0+1][n]}, b1 = {W[k0+8][n], W[k0+9][n]}; k0 = 16ks + 2(lane&3), n = 8nt + lane>>2
__global__ void prepack_kernel(const float* __restrict__ Wc2,
                               const float* __restrict__ Wp2,
                               const float* __restrict__ Wl1)
{
    int idx = blockIdx.x * blockDim.x + threadIdx.x;
    if (idx >= NP) return;
    const float* W; int p, N, ks, nt, lane;
    if (idx < OP2)      { W = Wc2; p = idx;       N = 256; ks = p >> 10; nt = (p >> 5) & 31; lane = p & 31; }
    else if (idx < OL1) { W = Wp2; p = idx - OP2; N = 256; ks = p >> 10; nt = (p >> 5) & 31; lane = p & 31; }
    else                { W = Wl1; p = idx - OL1; N = 128; ks = p >> 9;  nt = (p >> 5) & 15; lane = p & 31; }
    int k0 = 16 * ks + 2 * (lane & 3);
    int n  = 8 * nt + (lane >> 2);
    u32 lo = pkh2(W[k0 * N + n],       W[(k0 + 1) * N + n]);
    u32 hi = pkh2(W[(k0 + 8) * N + n], W[(k0 + 9) * N + n]);
    g_packed[idx] = ((u64)hi << 32) | (u64)lo;
}

// ---------- layer1: A[M][KA] @ W[KA][128] + b -> prelu -> U fp16 (u32 pairs) ----------
template<int M, int KA>
DEVINL void layer1(const float* __restrict__ A, const float* __restrict__ WS,
                   const float* __restrict__ bg, float alpha,
                   u32* __restrict__ Uu, int tx, int ty)
{
    constexpr int RPT = M / 16;
    float acc[RPT][2][2];
#pragma unroll
    for (int r = 0; r < RPT; r++)
#pragma unroll
        for (int jj = 0; jj < 2; jj++) { acc[r][jj][0] = 0.0f; acc[r][jj][1] = 0.0f; }

#pragma unroll
    for (int k = 0; k < KA; k += 4) {
        float a[RPT][4];
#pragma unroll
        for (int r = 0; r < RPT; r++) {
            float4 v = *(const float4*)&A[(ty * RPT + r) * KA + k];
            a[r][0] = v.x; a[r][1] = v.y; a[r][2] = v.z; a[r][3] = v.w;
        }
#pragma unroll
        for (int j4 = 0; j4 < 4; j4++) {
            float2 w0 = *(const float2*)&WS[(k + j4) * 128 + 2 * tx];
            float2 w1 = *(const float2*)&WS[(k + j4) * 128 + 2 * tx + 64];
#pragma unroll
            for (int r = 0; r < RPT; r++) {
                acc[r][0][0] = fmaf(a[r][j4], w0.x, acc[r][0][0]);
                acc[r][0][1] = fmaf(a[r][j4], w0.y, acc[r][0][1]);
                acc[r][1][0] = fmaf(a[r][j4], w1.x, acc[r][1][0]);
                acc[r][1][1] = fmaf(a[r][j4], w1.y, acc[r][1][1]);
            }
        }
    }
#pragma unroll
    for (int r = 0; r < RPT; r++)
#pragma unroll
        for (int jj = 0; jj < 2; jj++) {
            int cp = 2 * tx + 64 * jj;
            float v0 = acc[r][jj][0] + bg[cp];
            float v1 = acc[r][jj][1] + bg[cp + 1];
            v0 = (v0 >= 0.0f) ? v0 : alpha * v0;
            v1 = (v1 >= 0.0f) ? v1 : alpha * v1;
            Uu[(ty * RPT + r) * SU + tx + 32 * jj] = pkh2(v0, v1);
        }
}

// ---------- layer2: U[M][128] @ W[128][256] + b -> tanh -> CHPA fp16 ----------
// whole Wc2/Wp2 image resident; 8 barrier-free ksteps; warp: 2 m-tiles x NW n-tiles.
template<int M>
DEVINL void layer2(const u32* __restrict__ Uu, const u64* __restrict__ bt,
                   const float* __restrict__ bg, u32* __restrict__ CHu, int cOff2,
                   int tid)
{
    constexpr int NW = (M == 64) ? 4 : 2;
    const int w = tid >> 5, lane = tid & 31;
    const int r = lane >> 2, cth = lane & 3;
    const int mt0 = (M == 64) ? (w & 1) * 2 : 0;
    const int nb  = (M == 64) ? (w >> 1) * 4 : w * 2;

    float acc[2][NW][4];
#pragma unroll
    for (int mj = 0; mj < 2; mj++)
#pragma unroll
        for (int nj = 0; nj < NW; nj++)
#pragma unroll
            for (int q = 0; q < 4; q++) acc[mj][nj][q] = 0.0f;

#pragma unroll
    for (int ks = 0; ks < 8; ks++) {
        u32 a[2][4];
#pragma unroll
        for (int mj = 0; mj < 2; mj++) {
            int base = ((mt0 + mj) * 16 + r) * SU + ks * 8 + cth;
            a[mj][0] = Uu[base];
            a[mj][1] = Uu[base + 8 * SU];
            a[mj][2] = Uu[base + 4];
            a[mj][3] = Uu[base + 8 * SU + 4];
        }
#pragma unroll
        for (int nj = 0; nj < NW; nj++) {
            u64 b = bt[(ks * 32 + nb + nj) * 32 + lane];
#pragma unroll
            for (int mj = 0; mj < 2; mj++)
                mma16(acc[mj][nj], a[mj], (u32)b, (u32)(b >> 32));
        }
    }
#pragma unroll
    for (int mj = 0; mj < 2; mj++)
#pragma unroll
        for (int nj = 0; nj < NW; nj++) {
            int row0 = (mt0 + mj) * 16 + r;
            int c0 = (nb + nj) * 8 + 2 * cth;
            float b0v = bg[c0], b1v = bg[c0 + 1];
            u32 lo = pkh2(fast_tanh(acc[mj][nj][0] + b0v), fast_tanh(acc[mj][nj][1] + b1v));
            u32 hi = pkh2(fast_tanh(acc[mj][nj][2] + b0v), fast_tanh(acc[mj][nj][3] + b1v));
            CHu[row0 * SC + cOff2 + (nb + nj) * 4 + cth] = lo;
            CHu[(row0 + 8) * SC + cOff2 + (nb + nj) * 4 + cth] = hi;
        }
}

// ---------- layer3 pass: 16 ksteps (one 64KB Wl1 half); acc persists across passes ----------
template<int M>
DEVINL void layer3_pass(const u32* __restrict__ Cu, const u64* __restrict__ bt,
                        float (&acc)[2][2][4], int pass, int tid)
{
    constexpr int NW = (M == 64) ? 2 : 1;
    const int w = tid >> 5, lane = tid & 31;
    const int r = lane >> 2, cth = lane & 3;
    const int mt0 = (M == 64) ? (w & 1) * 2 : 0;
    const int nb  = (M == 64) ? (w >> 1) * 2 : w;

#pragma unroll 4
    for (int t = 0; t < 16; t++) {
        const int ksg = pass * 16 + t;
        u32 a[2][4];
#pragma unroll
        for (int mj = 0; mj < 2; mj++) {
            int base = ((mt0 + mj) * 16 + r) * SC + ksg * 8 + cth;
            a[mj][0] = Cu[base];
            a[mj][1] = Cu[base + 8 * SC];
            a[mj][2] = Cu[base + 4];
            a[mj][3] = Cu[base + 8 * SC + 4];
        }
#pragma unroll
        for (int nj = 0; nj < NW; nj++) {
            u64 b = bt[(t * 16 + nb + nj) * 32 + lane];
#pragma unroll
            for (int mj = 0; mj < 2; mj++)
                mma16(acc[mj][nj], a[mj], (u32)b, (u32)(b >> 32));
        }
    }
}

template<int M>
DEVINL void epi_l3(float (&acc)[2][2][4], const float* __restrict__ bl1,
                   float* __restrict__ H, int tid)
{
    constexpr int NW = (M == 64) ? 2 : 1;
    const int w = tid >> 5, lane = tid & 31;
    const int r = lane >> 2, cth = lane & 3;
    const int mt0 = (M == 64) ? (w & 1) * 2 : 0;
    const int nb  = (M == 64) ? (w >> 1) * 2 : w;
#pragma unroll
    for (int mj = 0; mj < 2; mj++)
#pragma unroll
        for (int nj = 0; nj < NW; nj++) {
            int row0 = (mt0 + mj) * 16 + r;
            int c0 = (nb + nj) * 8 + 2 * cth;
            float b0 = bl1[c0], b1 = bl1[c0 + 1];
            H[row0 * SH + c0]           = fast_tanh(acc[mj][nj][0] + b0);
            H[row0 * SH + c0 + 1]       = fast_tanh(acc[mj][nj][1] + b1);
            H[(row0 + 8) * SH + c0]     = fast_tanh(acc[mj][nj][2] + b0);
            H[(row0 + 8) * SH + c0 + 1] = fast_tanh(acc[mj][nj][3] + b1);
        }
}

// ---------- layer4: H[M][128] @ Wl2[128][32] + b -> prelu -> S12 / out ----------
template<int M, bool FINAL>
DEVINL void layer4(const float* __restrict__ H, const float* __restrict__ WS,
                   const float* __restrict__ bl2, float al,
                   float* __restrict__ S12, float* __restrict__ out,
                   int b0, int nb, int tx, int ty)
{
    constexpr int RPT = M / 16;
    float acc[RPT];
#pragma unroll
    for (int r = 0; r < RPT; r++) acc[r] = 0.0f;
#pragma unroll
    for (int k = 0; k < 128; k += 4) {
        float a[RPT][4];
#pragma unroll
        for (int r = 0; r < RPT; r++) {
            float4 v = *(const float4*)&H[(ty * RPT + r) * SH + k];
            a[r][0] = v.x; a[r][1] = v.y; a[r][2] = v.z; a[r][3] = v.w;
        }
#pragma unroll
        for (int j = 0; j < 4; j++) {
            float wv = WS[(k + j) * 32 + tx];
#pragma unroll
            for (int r = 0; r < RPT; r++) acc[r] = fmaf(a[r][j], wv, acc[r]);
        }
    }
#pragma unroll
    for (int r = 0; r < RPT; r++) {
        float v = acc[r] + bl2[tx];
        v = (v >= 0.0f) ? v : al * v;
        int row = ty * RPT + r;
        if (FINAL) {
            int be = b0 + (row >> 1);
            if (be < nb) out[(size_t)be * 64 + (row & 1) * 32 + tx] = v;
        } else {
            if (tx < 12) S12[row * 12 + tx] = v;
        }
    }
}

// ---------- full combine() pipeline ----------
template<int M, bool FINAL>
DEVINL void pipeline(float* sm, int tid,
                     const float* Wc1, const float* bc1, float ac, const float* bc2,
                     const float* Wp1, const float* bp1, float ap, const float* bp2,
                     const float* bl1, const float* Wl2, const float* bl2, float al,
                     float* out, int b0, int nb)
{
    u32*   Uu  = (u32*)(sm + SM_U);
    u32*   CHu = (u32*)(sm + SM_CHPA);
    float* H   = sm + SM_H;
    float* X   = sm + SM_H;          // staged by caller (dead after layer1)
    float* WT  = sm + SM_WT;
    const u64* bt = (const u64*)WT;
    float* WS  = sm + SM_WS;
    float* Y   = sm + SM_Y;
    float* S12 = sm + SM_S12;
    const int tx = tid & 31, ty = tid >> 5;
    const u64* G = g_packed;

    // child branch: WS <- Wc1, WT <- Wc2 frags
    load_ws(WS, Wc1, 24 * 128, tid); cpa_commit();
    load_wt(WT, G + OC2, tid); cpa_commit();
    cpa_wait1();
    __syncthreads();
    layer1<M, 24>(X, WS, bc1, ac, Uu, tx, ty);
    cpa_wait0();
    __syncthreads();
    layer2<M>(Uu, bt, bc2, CHu, 0, tid);
    __syncthreads();

    // parent branch: WS <- Wp1, WT <- Wp2 frags
    load_ws(WS, Wp1, 12 * 128, tid); cpa_commit();
    load_wt(WT, G + OP2, tid); cpa_commit();
    cpa_wait1();
    __syncthreads();
    layer1<M, 12>(Y, WS, bp1, ap, Uu, tx, ty);
    cpa_wait0();
    __syncthreads();
    layer2<M>(Uu, bt, bp2, CHu, 128, tid);   // colOff 256 -> u32 offset 128
    __syncthreads();

    // layer3: two 64KB halves of Wl1
    float acc[2][2][4];
#pragma unroll
    for (int a = 0; a < 2; a++)
#pragma unroll
        for (int b = 0; b < 2; b++)
#pragma unroll
            for (int q = 0; q < 4; q++) acc[a][b][q] = 0.0f;

    load_wt(WT, G + OL1, tid); cpa_commit();
    cpa_wait0();
    __syncthreads();
    layer3_pass<M>(CHu, bt, acc, 0, tid);
    __syncthreads();
    load_wt(WT, G + OL1 + 8192, tid); cpa_commit();
    load_ws(WS, Wl2, 128 * 32, tid); cpa_commit();
    cpa_wait0();
    __syncthreads();
    layer3_pass<M>(CHu, bt, acc, 1, tid);
    epi_l3<M>(acc, bl1, H, tid);
    __syncthreads();
    layer4<M, FINAL>(H, WS, bl2, al, S12, out, b0, nb, tx, ty);
}

__global__ void __launch_bounds__(NTH, 1)
rvnn_kernel(const float* __restrict__ level1, const float* __restrict__ level2,
            const float* __restrict__ level3,
            const float* __restrict__ Wc1, const float* __restrict__ bc1, const float* __restrict__ ac,
            const float* __restrict__ bc2,
            const float* __restrict__ Wp1, const float* __restrict__ bp1, const float* __restrict__ ap,
            const float* __restrict__ bp2,
            const float* __restrict__ bl1,
            const float* __restrict__ Wl2, const float* __restrict__ bl2, const float* __restrict__ al,
            float* __restrict__ out, int nb)
{
    extern __shared__ float sm[];
    const int tid = threadIdx.x;
    const int b0 = blockIdx.x * BB;
    const float acv = *ac, apv = *ap, alv = *al;

    float* X   = sm + SM_H;
    float* Y   = sm + SM_Y;
    float* S12 = sm + SM_S12;

    // ---- stage 1 staging: X 64x24 (pair-reversed level3), Y 64x12 (level2) ----
    {
        const float* src = level3 + (size_t)b0 * 96;
        int lim = (nb - b0 < BB ? nb - b0 : BB) * 96;
        for (int i = tid; i < BB * 96; i += NTH) {
            float v = (i < lim) ? sanf(src[i]) : 0.0f;
            int be = i / 96, rem = i % 96, c = rem / 12, k = rem % 12;
            int p = c >> 1, s = c & 1;
            X[(be * 4 + p) * 24 + (1 - s) * 12 + k] = v;
        }
    }
    {
        const float* src = level2 + (size_t)b0 * 48;
        int lim = (nb - b0 < BB ? nb - b0 : BB) * 48;
        for (int i = tid; i < BB * 48; i += NTH) {
            float v = (i < lim) ? sanf(src[i]) : 0.0f;
            int be = i / 48, rem = i % 48, p = rem / 12, k = rem % 12;
            Y[(be * 4 + p) * 12 + k] = v;
        }
    }
    __syncthreads();

    pipeline<64, false>(sm, tid, Wc1, bc1, acv, bc2, Wp1, bp1, apv,
                        bp2, bl1, Wl2, bl2, alv, out, b0, nb);
    __syncthreads();

    // ---- stage 2 staging: X 32x24 from S12 (pair-reversed), Y 32x12 (level1) ----
    for (int i = tid; i < 32 * 24; i += NTH) {
        int r2 = i / 24, k24 = i % 24, be = r2 >> 1, p = r2 & 1;
        int j = 2 * p + (k24 < 12 ? 1 : 0);
        int k = (k24 < 12) ? k24 : (k24 - 12);
        X[r2 * 24 + k24] = sanf(S12[(be * 4 + j) * 12 + k]);
    }
    {
        const float* src = level1 + (size_t)b0 * 24;
        int lim = (nb - b0 < BB ? nb - b0 : BB) * 24;
        for (int i = tid; i < BB * 24; i += NTH) {
            float v = (i < lim) ? sanf(src[i]) : 0.0f;
            int be = i / 24, rem = i % 24, p = rem / 12, k = rem % 12;
            Y[(be * 2 + p) * 12 + k] = v;
        }
    }
    __syncthreads();

    pipeline<32, true>(sm, tid, Wc1, bc1, acv, bc2, Wp1, bp1, apv,
                       bp2, bl1, Wl2, bl2, alv, out, b0, nb);
}

extern "C" void kernel_launch(void* const* d_in, const int* in_sizes, int n_in,
                              void* d_out, int out_size) {
    const float* level1 = (const float*)d_in[0];
    const float* level2 = (const float*)d_in[1];
    const float* level3 = (const float*)d_in[2];
    const float* Wc1 = (const float*)d_in[3];
    const float* bc1 = (const float*)d_in[4];
    const float* ac  = (const float*)d_in[5];
    const float* Wc2 = (const float*)d_in[6];
    const float* bc2 = (const float*)d_in[7];
    const float* Wp1 = (const float*)d_in[8];
    const float* bp1 = (const float*)d_in[9];
    const float* ap  = (const float*)d_in[10];
    const float* Wp2 = (const float*)d_in[11];
    const float* bp2 = (const float*)d_in[12];
    const float* Wl1 = (const float*)d_in[13];
    const float* bl1 = (const float*)d_in[14];
    const float* Wl2 = (const float*)d_in[15];
    const float* bl2 = (const float*)d_in[16];
    const float* al  = (const float*)d_in[17];
    float* out = (float*)d_out;

    int nb = in_sizes[0] / 24;
    int grid = (nb + BB - 1) / BB;
    size_t smem = (size_t)SM_TOT * sizeof(float);  // 205824 B

    prepack_kernel<<<(NP + 255) / 256, 256>>>(Wc2, Wp2, Wl1);

    cudaFuncSetAttribute(rvnn_kernel, cudaFuncAttributeMaxDynamicSharedMemorySize, (int)smem);
    rvnn_kernel<<<grid, NTH, smem>>>(level1, level2, level3, Wc1, bc1, ac, bc2,
                                     Wp1, bp1, ap, bp2, bl1, Wl2, bl2, al,
                                     out, nb);
}

// round 15
// speedup vs baseline: 2.5802x; 1.4045x over previous
#include <cuda_runtime.h>

// RvNN fused kernel v11: ALL layers on fp16 mma.sync m16n8k16.
// Layer1/layer4 converted from fp32 scalar to mma (inputs staged as fp16
// fragments, weights prepacked with zero-padded K). H stored fp16.
// Whole-layer weight images resident (64KB WT + 8KB WF), ~12 barriers/stage.

#define DEVINL __device__ __forceinline__
typedef unsigned int u32;
typedef unsigned long long u64;

constexpr int NTH = 512;
constexpr int BB  = 16;

// prepacked fp16 B-fragment images (u64 per (kstep16, n8tile, lane)):
constexpr int OC2  = 0;       // Wc2: 8 ks x 32 nt x 32 = 8192
constexpr int OP2  = 8192;    // Wp2: 8192
constexpr int OL1  = 16384;   // Wl1: 32 ks x 16 nt x 32 = 16384
constexpr int OWC1 = 32768;   // Wc1: 2 ks x 16 nt x 32 = 1024 (K=24 padded to 32)
constexpr int OWP1 = 33792;   // Wp1: 1 ks x 16 nt x 32 = 512  (K=12 padded to 16)
constexpr int OWL2 = 34304;   // Wl2: 8 ks x 4 nt x 32 = 1024
constexpr int NP   = 35328;
__device__ __align__(16) u64 g_packed[NP];

// ---- smem layout (float/u32 offsets) ----
constexpr int SXU = 20;      // Xh u32 row stride (16 pairs + pad, conflict-free)
constexpr int SYU = 12;      // Yh u32 row stride (8 pairs + pad)
constexpr int SU  = 68;      // U / H u32 row stride (64 pairs + pad)
constexpr int SC  = 260;     // CHPA u32 row stride (256 pairs + pad)
constexpr int SM_XH  = 0;        // 64 x 20 = 1280
constexpr int SM_YH  = 1280;     // 64 x 12 = 768
constexpr int SM_UU  = 2048;     // 64 x 68 = 4352
constexpr int SM_CH  = 6400;     // 64 x 260 = 16640
constexpr int SM_HU  = 23040;    // 64 x 68 = 4352
constexpr int SM_WT  = 27392;    // 16384 floats = 8192 u64 (64 KB)
constexpr int SM_WF  = 43776;    // 2048 floats = 1024 u64 (8 KB)
constexpr int SM_S12 = 45824;    // 768
constexpr int SM_TOT = 46592;    // 186368 bytes

DEVINL float sanf(float x) {
    if (isnan(x)) return 0.0f;
    if (isinf(x)) return 9999.0f;
    return x;
}
DEVINL float fast_tanh(float x) {
    float ax = fabsf(x) * 2.8853900817779268f;  // 2*log2(e)
    float e; asm("ex2.approx.f32 %0, %1;" : "=f"(e) : "f"(ax));
    float r; asm("rcp.approx.f32 %0, %1;" : "=f"(r) : "f"(e + 1.0f));
    float t = fmaf(-2.0f, r, 1.0f);
    return copysignf(t, x);
}
DEVINL u32 pkh2(float lo, float hi) {
    u32 r; asm("cvt.rn.f16x2.f32 %0, %1, %2;" : "=r"(r) : "f"(hi), "f"(lo)); return r;
}
DEVINL void mma16(float* d, const u32* a, u32 b0, u32 b1) {
    asm("mma.sync.aligned.m16n8k16.row.col.f32.f16.f16.f32 "
        "{%0,%1,%2,%3}, {%4,%5,%6,%7}, {%8,%9}, {%0,%1,%2,%3};"
        : "+f"(d[0]), "+f"(d[1]), "+f"(d[2]), "+f"(d[3])
        : "r"(a[0]), "r"(a[1]), "r"(a[2]), "r"(a[3]), "r"(b0), "r"(b1));
}
DEVINL void cpa16(void* dst, const void* src) {
    unsigned sa = (unsigned)__cvta_generic_to_shared(dst);
    asm volatile("cp.async.cg.shared.global [%0], [%1], 16;" :: "r"(sa), "l"(src));
}
DEVINL void cpa_commit() { asm volatile("cp.async.commit_group;"); }
DEVINL void cpa_wait0()  { asm volatile("cp.async.wait_group 0;"); }
DEVINL void cpa_wait1()  { asm volatile("cp.async.wait_group 1;"); }

// ---------- prepack: all six weights -> fp16 fragment u64 images ----------
__global__ void prepack_kernel(const float* __restrict__ Wc2, const float* __restrict__ Wp2,
                               const float* __restrict__ Wl1, const float* __restrict__ Wc1,
                               const float* __restrict__ Wp1, const float* __restrict__ Wl2)
{
    int idx = blockIdx.x * blockDim.x + threadIdx.x;
    if (idx >= NP) return;
    const float* W; int p, N, K, nts;
    if (idx < OP2)       { W = Wc2; p = idx;        N = 256; K = 128; nts = 32; }
    else if (idx < OL1)  { W = Wp2; p = idx - OP2;  N = 256; K = 128; nts = 32; }
    else if (idx < OWC1) { W = Wl1; p = idx - OL1;  N = 128; K = 512; nts = 16; }
    else if (idx < OWP1) { W = Wc1; p = idx - OWC1; N = 128; K = 24;  nts = 16; }
    else if (idx < OWL2) { W = Wp1; p = idx - OWP1; N = 128; K = 12;  nts = 16; }
    else                 { W = Wl2; p = idx - OWL2; N = 32;  K = 128; nts = 4;  }
    int lane = p & 31;
    int nt = (p >> 5) % nts;
    int ks = p / (32 * nts);
    int k0 = 16 * ks + 2 * (lane & 3);
    int n  = 8 * nt + (lane >> 2);
    float f0 = (k0     < K) ? W[k0 * N + n]       : 0.0f;
    float f1 = (k0 + 1 < K) ? W[(k0 + 1) * N + n] : 0.0f;
    float f2 = (k0 + 8 < K) ? W[(k0 + 8) * N + n] : 0.0f;
    float f3 = (k0 + 9 < K) ? W[(k0 + 9) * N + n] : 0.0f;
    u32 lo = pkh2(f0, f1);
    u32 hi = pkh2(f2, f3);
    g_packed[idx] = ((u64)hi << 32) | (u64)lo;
}

// ---------- layer1 (mma): Xh[M][K<=32] @ Wfrag -> prelu -> Uu fp16 ----------
template<int M, int KS>
DEVINL void layer1m(const u32* __restrict__ Xu, int sx, const u64* __restrict__ bt,
                    const float* __restrict__ bias, float alpha,
                    u32* __restrict__ Uu, int tid)
{
    constexpr int NW = (M == 64) ? 4 : 2;
    const int w = tid >> 5, lane = tid & 31;
    const int r = lane >> 2, cth = lane & 3;
    const int mi = (M == 64) ? (w & 3) : (w & 1);
    const int nb = (M == 64) ? (w >> 2) * NW : (w >> 1) * NW;
    float acc[NW][4];
#pragma unroll
    for (int nj = 0; nj < NW; nj++)
#pragma unroll
        for (int q = 0; q < 4; q++) acc[nj][q] = 0.0f;

#pragma unroll
    for (int ks = 0; ks < KS; ks++) {
        int base = (mi * 16 + r) * sx + ks * 8 + cth;
        u32 a[4];
        a[0] = Xu[base];
        a[1] = Xu[base + 8 * sx];
        a[2] = Xu[base + 4];
        a[3] = Xu[base + 8 * sx + 4];
#pragma unroll
        for (int nj = 0; nj < NW; nj++) {
            u64 b = bt[(ks * 16 + nb + nj) * 32 + lane];
            mma16(acc[nj], a, (u32)b, (u32)(b >> 32));
        }
    }
#pragma unroll
    for (int nj = 0; nj < NW; nj++) {
        int c0 = (nb + nj) * 8 + 2 * cth;
        float b0v = bias[c0], b1v = bias[c0 + 1];
        float v0 = acc[nj][0] + b0v, v1 = acc[nj][1] + b1v;
        float v2 = acc[nj][2] + b0v, v3 = acc[nj][3] + b1v;
        v0 = (v0 >= 0.0f) ? v0 : alpha * v0;
        v1 = (v1 >= 0.0f) ? v1 : alpha * v1;
        v2 = (v2 >= 0.0f) ? v2 : alpha * v2;
        v3 = (v3 >= 0.0f) ? v3 : alpha * v3;
        int row0 = mi * 16 + r;
        Uu[row0 * SU + (nb + nj) * 4 + cth] = pkh2(v0, v1);
        Uu[(row0 + 8) * SU + (nb + nj) * 4 + cth] = pkh2(v2, v3);
    }
}

// ---------- layer2: U[M][128] @ W[128][256] + b -> tanh -> CHPA fp16 ----------
template<int M>
DEVINL void layer2(const u32* __restrict__ Uu, const u64* __restrict__ bt,
                   const float* __restrict__ bg, u32* __restrict__ CHu, int cOff2,
                   int tid)
{
    constexpr int NW = (M == 64) ? 4 : 2;
    const int w = tid >> 5, lane = tid & 31;
    const int r = lane >> 2, cth = lane & 3;
    const int mt0 = (M == 64) ? (w & 1) * 2 : 0;
    const int nb  = (M == 64) ? (w >> 1) * 4 : w * 2;

    float acc[2][NW][4];
#pragma unroll
    for (int mj = 0; mj < 2; mj++)
#pragma unroll
        for (int nj = 0; nj < NW; nj++)
#pragma unroll
            for (int q = 0; q < 4; q++) acc[mj][nj][q] = 0.0f;

#pragma unroll
    for (int ks = 0; ks < 8; ks++) {
        u32 a[2][4];
#pragma unroll
        for (int mj = 0; mj < 2; mj++) {
            int base = ((mt0 + mj) * 16 + r) * SU + ks * 8 + cth;
            a[mj][0] = Uu[base];
            a[mj][1] = Uu[base + 8 * SU];
            a[mj][2] = Uu[base + 4];
            a[mj][3] = Uu[base + 8 * SU + 4];
        }
#pragma unroll
        for (int nj = 0; nj < NW; nj++) {
            u64 b = bt[(ks * 32 + nb + nj) * 32 + lane];
#pragma unroll
            for (int mj = 0; mj < 2; mj++)
                mma16(acc[mj][nj], a[mj], (u32)b, (u32)(b >> 32));
        }
    }
#pragma unroll
    for (int mj = 0; mj < 2; mj++)
#pragma unroll
        for (int nj = 0; nj < NW; nj++) {
            int row0 = (mt0 + mj) * 16 + r;
            int c0 = (nb + nj) * 8 + 2 * cth;
            float b0v = bg[c0], b1v = bg[c0 + 1];
            u32 lo = pkh2(fast_tanh(acc[mj][nj][0] + b0v), fast_tanh(acc[mj][nj][1] + b1v));
            u32 hi = pkh2(fast_tanh(acc[mj][nj][2] + b0v), fast_tanh(acc[mj][nj][3] + b1v));
            CHu[row0 * SC + cOff2 + (nb + nj) * 4 + cth] = lo;
            CHu[(row0 + 8) * SC + cOff2 + (nb + nj) * 4 + cth] = hi;
        }
}

// ---------- layer3 pass: 16 ksteps (one 64KB Wl1 half); acc persists ----------
template<int M>
DEVINL void layer3_pass(const u32* __restrict__ Cu, const u64* __restrict__ bt,
                        float (&acc)[2][2][4], int pass, int tid)
{
    constexpr int NW = (M == 64) ? 2 : 1;
    const int w = tid >> 5, lane = tid & 31;
    const int r = lane >> 2, cth = lane & 3;
    const int mt0 = (M == 64) ? (w & 1) * 2 : 0;
    const int nb  = (M == 64) ? (w >> 1) * 2 : w;

#pragma unroll 4
    for (int t = 0; t < 16; t++) {
        const int ksg = pass * 16 + t;
        u32 a[2][4];
#pragma unroll
        for (int mj = 0; mj < 2; mj++) {
            int base = ((mt0 + mj) * 16 + r) * SC + ksg * 8 + cth;
            a[mj][0] = Cu[base];
            a[mj][1] = Cu[base + 8 * SC];
            a[mj][2] = Cu[base + 4];
            a[mj][3] = Cu[base + 8 * SC + 4];
        }
#pragma unroll
        for (int nj = 0; nj < NW; nj++) {
            u64 b = bt[(t * 16 + nb + nj) * 32 + lane];
#pragma unroll
            for (int mj = 0; mj < 2; mj++)
                mma16(acc[mj][nj], a[mj], (u32)b, (u32)(b >> 32));
        }
    }
}

// ---------- epi_l3: acc -> tanh -> Hu fp16 ----------
template<int M>
DEVINL void epi_l3(float (&acc)[2][2][4], const float* __restrict__ bl1,
                   u32* __restrict__ Hu, int tid)
{
    constexpr int NW = (M == 64) ? 2 : 1;
    const int w = tid >> 5, lane = tid & 31;
    const int r = lane >> 2, cth = lane & 3;
    const int mt0 = (M == 64) ? (w & 1) * 2 : 0;
    const int nb  = (M == 64) ? (w >> 1) * 2 : w;
#pragma unroll
    for (int mj = 0; mj < 2; mj++)
#pragma unroll
        for (int nj = 0; nj < NW; nj++) {
            int row0 = (mt0 + mj) * 16 + r;
            int c0 = (nb + nj) * 8 + 2 * cth;
            float b0 = bl1[c0], b1 = bl1[c0 + 1];
            u32 lo = pkh2(fast_tanh(acc[mj][nj][0] + b0), fast_tanh(acc[mj][nj][1] + b1));
            u32 hi = pkh2(fast_tanh(acc[mj][nj][2] + b0), fast_tanh(acc[mj][nj][3] + b1));
            Hu[row0 * SU + (nb + nj) * 4 + cth] = lo;
            Hu[(row0 + 8) * SU + (nb + nj) * 4 + cth] = hi;
        }
}

// ---------- layer4 (mma): Hu[M][128] @ Wl2frag -> prelu -> S12 / out ----------
template<int M, bool FINAL>
DEVINL void layer4m(const u32* __restrict__ Hu, const u64* __restrict__ bt,
                    const float* __restrict__ bl2, float al,
                    float* __restrict__ S12, float* __restrict__ out,
                    int b0, int nbat, int tid)
{
    const int w = tid >> 5, lane = tid & 31;
    const int r = lane >> 2, cth = lane & 3;
    int mi, nt; bool act;
    if (M == 64) { mi = w & 3; nt = w >> 2; act = true; }
    else         { mi = w & 1; nt = w >> 1; act = (w < 8); }
    if (!act) return;
    float acc[4] = {0.0f, 0.0f, 0.0f, 0.0f};
#pragma unroll
    for (int ks = 0; ks < 8; ks++) {
        int base = (mi * 16 + r) * SU + ks * 8 + cth;
        u32 a[4];
        a[0] = Hu[base];
        a[1] = Hu[base + 8 * SU];
        a[2] = Hu[base + 4];
        a[3] = Hu[base + 8 * SU + 4];
        u64 b = bt[(ks * 4 + nt) * 32 + lane];
        mma16(acc, a, (u32)b, (u32)(b >> 32));
    }
    int c0 = nt * 8 + 2 * cth;
    float b0v = bl2[c0], b1v = bl2[c0 + 1];
    float vv[4] = { acc[0] + b0v, acc[1] + b1v, acc[2] + b0v, acc[3] + b1v };
#pragma unroll
    for (int q = 0; q < 4; q++) vv[q] = (vv[q] >= 0.0f) ? vv[q] : al * vv[q];
    int rows[2] = { mi * 16 + r, mi * 16 + r + 8 };
#pragma unroll
    for (int h = 0; h < 2; h++) {
        int row = rows[h];
#pragma unroll
        for (int e = 0; e < 2; e++) {
            int c = c0 + e;
            float v = vv[h * 2 + e];
            if (FINAL) {
                int be = b0 + (row >> 1);
                if (be < nbat) out[(size_t)be * 64 + (row & 1) * 32 + c] = v;
            } else {
                if (c < 12) S12[row * 12 + c] = v;
            }
        }
    }
}

// ---------- full combine() pipeline ----------
template<int M, bool FINAL>
DEVINL void pipeline(float* sm, int tid,
                     const float* bc1, float ac, const float* bc2,
                     const float* bp1, float ap, const float* bp2,
                     const float* bl1, const float* bl2, float al,
                     float* out, int b0, int nbat)
{
    u32* Xu  = (u32*)(sm + SM_XH);
    u32* Yu  = (u32*)(sm + SM_YH);
    u32* Uu  = (u32*)(sm + SM_UU);
    u32* CHu = (u32*)(sm + SM_CH);
    u32* Hu  = (u32*)(sm + SM_HU);
    u64* WTd = (u64*)(sm + SM_WT);
    u64* WFd = (u64*)(sm + SM_WF);
    float* S12 = sm + SM_S12;
    const u64* G = g_packed;

    // child: WF <- Wc1 frags, WT <- Wc2 frags
    for (int s = tid; s < 512; s += NTH)  cpa16(WFd + s * 2, G + OWC1 + s * 2);
    cpa_commit();
    for (int s = tid; s < 4096; s += NTH) cpa16(WTd + s * 2, G + OC2 + s * 2);
    cpa_commit();
    cpa_wait1();
    __syncthreads();
    layer1m<M, 2>(Xu, SXU, WFd, bc1, ac, Uu, tid);
    cpa_wait0();
    __syncthreads();
    layer2<M>(Uu, WTd, bc2, CHu, 0, tid);
    __syncthreads();

    // parent: WF <- Wp1 frags, WT <- Wp2 frags
    for (int s = tid; s < 256; s += NTH)  cpa16(WFd + s * 2, G + OWP1 + s * 2);
    cpa_commit();
    for (int s = tid; s < 4096; s += NTH) cpa16(WTd + s * 2, G + OP2 + s * 2);
    cpa_commit();
    cpa_wait1();
    __syncthreads();
    layer1m<M, 1>(Yu, SYU, WFd, bp1, ap, Uu, tid);
    cpa_wait0();
    __syncthreads();
    layer2<M>(Uu, WTd, bp2, CHu, 128, tid);
    __syncthreads();

    // layer3: two 64KB halves of Wl1; WF <- Wl2 frags
    float acc[2][2][4];
#pragma unroll
    for (int a = 0; a < 2; a++)
#pragma unroll
        for (int b = 0; b < 2; b++)
#pragma unroll
            for (int q = 0; q < 4; q++) acc[a][b][q] = 0.0f;

    for (int s = tid; s < 4096; s += NTH) cpa16(WTd + s * 2, G + OL1 + s * 2);
    cpa_commit();
    for (int s = tid; s < 512; s += NTH)  cpa16(WFd + s * 2, G + OWL2 + s * 2);
    cpa_commit();
    cpa_wait1();
    __syncthreads();
    layer3_pass<M>(CHu, WTd, acc, 0, tid);
    __syncthreads();
    for (int s = tid; s < 4096; s += NTH) cpa16(WTd + s * 2, G + OL1 + 8192 + s * 2);
    cpa_commit();
    cpa_wait0();
    __syncthreads();
    layer3_pass<M>(CHu, WTd, acc, 1, tid);
    epi_l3<M>(acc, bl1, Hu, tid);
    __syncthreads();
    layer4m<M, FINAL>(Hu, WFd, bl2, al, S12, out, b0, nbat, tid);
}

__global__ void __launch_bounds__(NTH, 1)
rvnn_kernel(const float* __restrict__ level1, const float* __restrict__ level2,
            const float* __restrict__ level3,
            const float* __restrict__ bc1, const float* __restrict__ ac,
            const float* __restrict__ bc2,
            const float* __restrict__ bp1, const float* __restrict__ ap,
            const float* __restrict__ bp2,
            const float* __restrict__ bl1,
            const float* __restrict__ bl2, const float* __restrict__ al,
            float* __restrict__ out, int nbat)
{
    extern __shared__ float sm[];
    const int tid = threadIdx.x;
    const int b0 = blockIdx.x * BB;
    const float acv = *ac, apv = *ap, alv = *al;

    u32* Xu  = (u32*)(sm + SM_XH);
    u32* Yu  = (u32*)(sm + SM_YH);
    float* S12 = sm + SM_S12;

    // ---- stage 1 staging: Xh 64x16 pairs (pair-reversed level3), Yh 64x8 (level2) ----
    {
        const float* src = level3 + (size_t)b0 * 96;
        int lim = (nbat - b0 < BB ? nbat - b0 : BB) * 96;
        for (int i = tid; i < 64 * 16; i += NTH) {
            int row = i >> 4, j = i & 15;
            u32 val = 0;
            if (j < 12) {
                int be = row >> 2, p = row & 3;
                int cs, k;
                if (j < 6) { cs = 2 * p + 1; k = 2 * j; }
                else       { cs = 2 * p;     k = 2 * j - 12; }
                int gi = be * 96 + cs * 12 + k;
                float v0 = (gi < lim) ? sanf(src[gi]) : 0.0f;
                float v1 = (gi + 1 < lim) ? sanf(src[gi + 1]) : 0.0f;
                val = pkh2(v0, v1);
            }
            Xu[row * SXU + j] = val;
        }
    }
    {
        const float* src = level2 + (size_t)b0 * 48;
        int lim = (nbat - b0 < BB ? nbat - b0 : BB) * 48;
        for (int i = tid; i < 64 * 8; i += NTH) {
            int row = i >> 3, j = i & 7;
            u32 val = 0;
            if (j < 6) {
                int be = row >> 2, p = row & 3;
                int gi = be * 48 + p * 12 + 2 * j;
                float v0 = (gi < lim) ? sanf(src[gi]) : 0.0f;
                float v1 = (gi + 1 < lim) ? sanf(src[gi + 1]) : 0.0f;
                val = pkh2(v0, v1);
            }
            Yu[row * SYU + j] = val;
        }
    }
    __syncthreads();

    pipeline<64, false>(sm, tid, bc1, acv, bc2, bp1, apv, bp2, bl1, bl2, alv,
                        out, b0, nbat);
    __syncthreads();

    // ---- stage 2 staging: Xh 32x16 from S12 (pair-reversed), Yh 32x8 (level1) ----
    for (int i = tid; i < 32 * 16; i += NTH) {
        int row = i >> 4, j = i & 15;
        u32 val = 0;
        if (j < 12) {
            int be = row >> 1, p = row & 1;
            int jj, k;
            if (j < 6) { jj = 2 * p + 1; k = 2 * j; }
            else       { jj = 2 * p;     k = 2 * j - 12; }
            float v0 = sanf(S12[(be * 4 + jj) * 12 + k]);
            float v1 = sanf(S12[(be * 4 + jj) * 12 + k + 1]);
            val = pkh2(v0, v1);
        }
        Xu[row * SXU + j] = val;
    }
    {
        const float* src = level1 + (size_t)b0 * 24;
        int lim = (nbat - b0 < BB ? nbat - b0 : BB) * 24;
        for (int i = tid; i < 32 * 8; i += NTH) {
            int row = i >> 3, j = i & 7;
            u32 val = 0;
            if (j < 6) {
                int be = row >> 1, p = row & 1;
                int gi = be * 24 + p * 12 + 2 * j;
                float v0 = (gi < lim) ? sanf(src[gi]) : 0.0f;
                float v1 = (gi + 1 < lim) ? sanf(src[gi + 1]) : 0.0f;
                val = pkh2(v0, v1);
            }
            Yu[row * SYU + j] = val;
        }
    }
    __syncthreads();

    pipeline<32, true>(sm, tid, bc1, acv, bc2, bp1, apv, bp2, bl1, bl2, alv,
                       out, b0, nbat);
}

extern "C" void kernel_launch(void* const* d_in, const int* in_sizes, int n_in,
                              void* d_out, int out_size) {
    const float* level1 = (const float*)d_in[0];
    const float* level2 = (const float*)d_in[1];
    const float* level3 = (const float*)d_in[2];
    const float* Wc1 = (const float*)d_in[3];
    const float* bc1 = (const float*)d_in[4];
    const float* ac  = (const float*)d_in[5];
    const float* Wc2 = (const float*)d_in[6];
    const float* bc2 = (const float*)d_in[7];
    const float* Wp1 = (const float*)d_in[8];
    const float* bp1 = (const float*)d_in[9];
    const float* ap  = (const float*)d_in[10];
    const float* Wp2 = (const float*)d_in[11];
    const float* bp2 = (const float*)d_in[12];
    const float* Wl1 = (const float*)d_in[13];
    const float* bl1 = (const float*)d_in[14];
    const float* Wl2 = (const float*)d_in[15];
    const float* bl2 = (const float*)d_in[16];
    const float* al  = (const float*)d_in[17];
    float* out = (float*)d_out;

    int nbat = in_sizes[0] / 24;
    int grid = (nbat + BB - 1) / BB;
    size_t smem = (size_t)SM_TOT * sizeof(float);  // 186368 B

    prepack_kernel<<<(NP + 255) / 256, 256>>>(Wc2, Wp2, Wl1, Wc1, Wp1, Wl2);

    cudaFuncSetAttribute(rvnn_kernel, cudaFuncAttributeMaxDynamicSharedMemorySize, (int)smem);
    rvnn_kernel<<<grid, NTH, smem>>>(level1, level2, level3, bc1, ac, bc2,
                                     bp1, ap, bp2, bl1, bl2, al, out, nbat);
}

// round 17
// speedup vs baseline: 2.5983x; 1.0070x over previous
#include <cuda_runtime.h>

// RvNN fused kernel v12 (re-bench, byte-identical: prior round was a container
// failure; audit found no kernel-attributable defect).
// v11 (all-fp16 mma) + ldmatrix.x4 A-fragment loads + fully overlapped weight
// streaming (Wl1 in 4x32KB double-buffered quarters, Wc2 prefetched).

#define DEVINL __device__ __forceinline__
typedef unsigned int u32;
typedef unsigned long long u64;

constexpr int NTH = 512;
constexpr int BB  = 16;

// prepacked fp16 B-fragment images (u64 per (kstep16, n8tile, lane)):
constexpr int OC2  = 0;       // Wc2: 8 ks x 32 nt x 32 = 8192
constexpr int OP2  = 8192;    // Wp2: 8192
constexpr int OL1  = 16384;   // Wl1: 32 ks x 16 nt x 32 = 16384
constexpr int OWC1 = 32768;   // Wc1: 2 ks x 16 nt x 32 = 1024 (K=24 padded)
constexpr int OWP1 = 33792;   // Wp1: 1 ks x 16 nt x 32 = 512  (K=12 padded)
constexpr int OWL2 = 34304;   // Wl2: 8 ks x 4 nt x 32 = 1024
constexpr int NP   = 35328;
__device__ __align__(16) u64 g_packed[NP];

// ---- smem layout (float/u32 offsets) ----
constexpr int SXU = 20;      // Xh u32 row stride
constexpr int SYU = 12;      // Yh u32 row stride
constexpr int SU  = 68;      // U / H u32 row stride
constexpr int SC  = 260;     // CHPA u32 row stride
constexpr int SM_XH  = 0;        // 1280
constexpr int SM_YH  = 1280;     // 768
constexpr int SM_UU  = 2048;     // 4352
constexpr int SM_CH  = 6400;     // 16640
constexpr int SM_HU  = 23040;    // 4352
constexpr int SM_WT  = 27392;    // 16384 floats = 8192 u64 (64 KB)
constexpr int SM_WTB = 43776;    // 8192 floats = 4096 u64 (32 KB)
constexpr int SM_WF  = 51968;    // 2048 floats = 1024 u64 (8 KB)
constexpr int SM_S12 = 54016;    // 768
constexpr int SM_TOT = 54784;    // 219136 bytes

DEVINL float sanf(float x) {
    if (isnan(x)) return 0.0f;
    if (isinf(x)) return 9999.0f;
    return x;
}
DEVINL float fast_tanh(float x) {
    float ax = fabsf(x) * 2.8853900817779268f;  // 2*log2(e)
    float e; asm("ex2.approx.f32 %0, %1;" : "=f"(e) : "f"(ax));
    float r; asm("rcp.approx.f32 %0, %1;" : "=f"(r) : "f"(e + 1.0f));
    float t = fmaf(-2.0f, r, 1.0f);
    return copysignf(t, x);
}
DEVINL u32 pkh2(float lo, float hi) {
    u32 r; asm("cvt.rn.f16x2.f32 %0, %1, %2;" : "=r"(r) : "f"(hi), "f"(lo)); return r;
}
DEVINL u32 s2u(const void* p) {
    u32 a;
    asm("{ .reg .u64 t; cvta.to.shared.u64 t, %1; cvt.u32.u64 %0, t; }" : "=r"(a) : "l"(p));
    return a;
}
DEVINL void mma16(float* d, const u32* a, u32 b0, u32 b1) {
    asm("mma.sync.aligned.m16n8k16.row.col.f32.f16.f16.f32 "
        "{%0,%1,%2,%3}, {%4,%5,%6,%7}, {%8,%9}, {%0,%1,%2,%3};"
        : "+f"(d[0]), "+f"(d[1]), "+f"(d[2]), "+f"(d[3])
        : "r"(a[0]), "r"(a[1]), "r"(a[2]), "r"(a[3]), "r"(b0), "r"(b1));
}
// load 4 A-fragments (m16 x k16) in one instruction
DEVINL void ldmA(u32* a, u32 sa) {
    asm volatile("ldmatrix.sync.aligned.m8n8.x4.shared.b16 {%0,%1,%2,%3}, [%4];"
        : "=r"(a[0]), "=r"(a[1]), "=r"(a[2]), "=r"(a[3]) : "r"(sa));
}
DEVINL void cpa16(void* dst, const void* src) {
    unsigned sa = (unsigned)__cvta_generic_to_shared(dst);
    asm volatile("cp.async.cg.shared.global [%0], [%1], 16;" :: "r"(sa), "l"(src));
}
DEVINL void cpa_commit() { asm volatile("cp.async.commit_group;"); }
DEVINL void cpa_wait0()  { asm volatile("cp.async.wait_group 0;"); }
DEVINL void cpa_wait1()  { asm volatile("cp.async.wait_group 1;"); }

// lane's ldmatrix row/col selector: mat g = lane>>3; row = ((g&1)<<3)+(lane&7); col4 = (g>>1)<<2
DEVINL int ldm_row(int lane) { int g = lane >> 3; return ((g & 1) << 3) + (lane & 7); }
DEVINL int ldm_col(int lane) { return ((lane >> 4) << 2); }

// ---------- prepack: all six weights -> fp16 fragment u64 images ----------
__global__ void prepack_kernel(const float* __restrict__ Wc2, const float* __restrict__ Wp2,
                               const float* __restrict__ Wl1, const float* __restrict__ Wc1,
                               const float* __restrict__ Wp1, const float* __restrict__ Wl2)
{
    int idx = blockIdx.x * blockDim.x + threadIdx.x;
    if (idx >= NP) return;
    const float* W; int p, N, K, nts;
    if (idx < OP2)       { W = Wc2; p = idx;        N = 256; K = 128; nts = 32; }
    else if (idx < OL1)  { W = Wp2; p = idx - OP2;  N = 256; K = 128; nts = 32; }
    else if (idx < OWC1) { W = Wl1; p = idx - OL1;  N = 128; K = 512; nts = 16; }
    else if (idx < OWP1) { W = Wc1; p = idx - OWC1; N = 128; K = 24;  nts = 16; }
    else if (idx < OWL2) { W = Wp1; p = idx - OWP1; N = 128; K = 12;  nts = 16; }
    else                 { W = Wl2; p = idx - OWL2; N = 32;  K = 128; nts = 4;  }
    int lane = p & 31;
    int nt = (p >> 5) % nts;
    int ks = p / (32 * nts);
    int k0 = 16 * ks + 2 * (lane & 3);
    int n  = 8 * nt + (lane >> 2);
    float f0 = (k0     < K) ? W[k0 * N + n]       : 0.0f;
    float f1 = (k0 + 1 < K) ? W[(k0 + 1) * N + n] : 0.0f;
    float f2 = (k0 + 8 < K) ? W[(k0 + 8) * N + n] : 0.0f;
    float f3 = (k0 + 9 < K) ? W[(k0 + 9) * N + n] : 0.0f;
    u32 lo = pkh2(f0, f1);
    u32 hi = pkh2(f2, f3);
    g_packed[idx] = ((u64)hi << 32) | (u64)lo;
}

// ---------- layer1 (mma): X[M][K<=32] @ Wfrag -> prelu -> Uu fp16 ----------
template<int M, int KS, int SX>
DEVINL void layer1m(u32 xbase, const u64* __restrict__ bt,
                    const float* __restrict__ bias, float alpha,
                    u32* __restrict__ Uu, int tid)
{
    constexpr int NW = (M == 64) ? 4 : 2;
    const int w = tid >> 5, lane = tid & 31;
    const int r = lane >> 2, cth = lane & 3;
    const int mi = (M == 64) ? (w & 3) : (w & 1);
    const int nb = (M == 64) ? (w >> 2) * NW : (w >> 1) * NW;
    const u32 ab = xbase + 4u * (u32)(mi * 16 * SX + ldm_row(lane) * SX + ldm_col(lane));
    float acc[NW][4];
#pragma unroll
    for (int nj = 0; nj < NW; nj++)
#pragma unroll
        for (int q = 0; q < 4; q++) acc[nj][q] = 0.0f;

#pragma unroll
    for (int ks = 0; ks < KS; ks++) {
        u32 a[4];
        ldmA(a, ab + 4u * (u32)(ks * 8));
#pragma unroll
        for (int nj = 0; nj < NW; nj++) {
            u64 b = bt[(ks * 16 + nb + nj) * 32 + lane];
            mma16(acc[nj], a, (u32)b, (u32)(b >> 32));
        }
    }
#pragma unroll
    for (int nj = 0; nj < NW; nj++) {
        int c0 = (nb + nj) * 8 + 2 * cth;
        float b0v = bias[c0], b1v = bias[c0 + 1];
        float v0 = acc[nj][0] + b0v, v1 = acc[nj][1] + b1v;
        float v2 = acc[nj][2] + b0v, v3 = acc[nj][3] + b1v;
        v0 = (v0 >= 0.0f) ? v0 : alpha * v0;
        v1 = (v1 >= 0.0f) ? v1 : alpha * v1;
        v2 = (v2 >= 0.0f) ? v2 : alpha * v2;
        v3 = (v3 >= 0.0f) ? v3 : alpha * v3;
        int row0 = mi * 16 + r;
        Uu[row0 * SU + (nb + nj) * 4 + cth] = pkh2(v0, v1);
        Uu[(row0 + 8) * SU + (nb + nj) * 4 + cth] = pkh2(v2, v3);
    }
}

// ---------- layer2: U[M][128] @ W[128][256] + b -> tanh -> CHPA fp16 ----------
template<int M>
DEVINL void layer2(u32 ubase, const u64* __restrict__ bt,
                   const float* __restrict__ bg, u32* __restrict__ CHu, int cOff2,
                   int tid)
{
    constexpr int NW = (M == 64) ? 4 : 2;
    const int w = tid >> 5, lane = tid & 31;
    const int r = lane >> 2, cth = lane & 3;
    const int mt0 = (M == 64) ? (w & 1) * 2 : 0;
    const int nb  = (M == 64) ? (w >> 1) * 4 : w * 2;
    const u32 ab = ubase + 4u * (u32)(mt0 * 16 * SU + ldm_row(lane) * SU + ldm_col(lane));

    float acc[2][NW][4];
#pragma unroll
    for (int mj = 0; mj < 2; mj++)
#pragma unroll
        for (int nj = 0; nj < NW; nj++)
#pragma unroll
            for (int q = 0; q < 4; q++) acc[mj][nj][q] = 0.0f;

#pragma unroll
    for (int ks = 0; ks < 8; ks++) {
        u32 a[2][4];
#pragma unroll
        for (int mj = 0; mj < 2; mj++)
            ldmA(a[mj], ab + 4u * (u32)(mj * 16 * SU + ks * 8));
#pragma unroll
        for (int nj = 0; nj < NW; nj++) {
            u64 b = bt[(ks * 32 + nb + nj) * 32 + lane];
#pragma unroll
            for (int mj = 0; mj < 2; mj++)
                mma16(acc[mj][nj], a[mj], (u32)b, (u32)(b >> 32));
        }
    }
#pragma unroll
    for (int mj = 0; mj < 2; mj++)
#pragma unroll
        for (int nj = 0; nj < NW; nj++) {
            int row0 = (mt0 + mj) * 16 + r;
            int c0 = (nb + nj) * 8 + 2 * cth;
            float b0v = bg[c0], b1v = bg[c0 + 1];
            u32 lo = pkh2(fast_tanh(acc[mj][nj][0] + b0v), fast_tanh(acc[mj][nj][1] + b1v));
            u32 hi = pkh2(fast_tanh(acc[mj][nj][2] + b0v), fast_tanh(acc[mj][nj][3] + b1v));
            CHu[row0 * SC + cOff2 + (nb + nj) * 4 + cth] = lo;
            CHu[(row0 + 8) * SC + cOff2 + (nb + nj) * 4 + cth] = hi;
        }
}

// ---------- layer3 quarter pass: 8 ksteps on a 32KB chunk; acc persists ----------
template<int M>
DEVINL void layer3_q(u32 cbase, const u64* __restrict__ bt,
                     float (&acc)[2][2][4], int q, int tid)
{
    constexpr int NW = (M == 64) ? 2 : 1;
    const int w = tid >> 5, lane = tid & 31;
    const int mt0 = (M == 64) ? (w & 1) * 2 : 0;
    const int nb  = (M == 64) ? (w >> 1) * 2 : w;
    const u32 ab = cbase + 4u * (u32)(mt0 * 16 * SC + ldm_row(lane) * SC + ldm_col(lane));

#pragma unroll
    for (int t = 0; t < 8; t++) {
        const int ksg = q * 8 + t;
        u32 a[2][4];
#pragma unroll
        for (int mj = 0; mj < 2; mj++)
            ldmA(a[mj], ab + 4u * (u32)(mj * 16 * SC + ksg * 8));
#pragma unroll
        for (int nj = 0; nj < NW; nj++) {
            u64 b = bt[(t * 16 + nb + nj) * 32 + lane];
#pragma unroll
            for (int mj = 0; mj < 2; mj++)
                mma16(acc[mj][nj], a[mj], (u32)b, (u32)(b >> 32));
        }
    }
}

// ---------- epi_l3: acc -> tanh -> Hu fp16 ----------
template<int M>
DEVINL void epi_l3(float (&acc)[2][2][4], const float* __restrict__ bl1,
                   u32* __restrict__ Hu, int tid)
{
    constexpr int NW = (M == 64) ? 2 : 1;
    const int w = tid >> 5, lane = tid & 31;
    const int r = lane >> 2, cth = lane & 3;
    const int mt0 = (M == 64) ? (w & 1) * 2 : 0;
    const int nb  = (M == 64) ? (w >> 1) * 2 : w;
#pragma unroll
    for (int mj = 0; mj < 2; mj++)
#pragma unroll
        for (int nj = 0; nj < NW; nj++) {
            int row0 = (mt0 + mj) * 16 + r;
            int c0 = (nb + nj) * 8 + 2 * cth;
            float b0 = bl1[c0], b1 = bl1[c0 + 1];
            u32 lo = pkh2(fast_tanh(acc[mj][nj][0] + b0), fast_tanh(acc[mj][nj][1] + b1));
            u32 hi = pkh2(fast_tanh(acc[mj][nj][2] + b0), fast_tanh(acc[mj][nj][3] + b1));
            Hu[row0 * SU + (nb + nj) * 4 + cth] = lo;
            Hu[(row0 + 8) * SU + (nb + nj) * 4 + cth] = hi;
        }
}

// ---------- layer4 (mma): Hu[M][128] @ Wl2frag -> prelu -> S12 / out ----------
template<int M, bool FINAL>
DEVINL void layer4m(u32 hbase, const u64* __restrict__ bt,
                    const float* __restrict__ bl2, float al,
                    float* __restrict__ S12, float* __restrict__ out,
                    int b0, int nbat, int tid)
{
    const int w = tid >> 5, lane = tid & 31;
    const int r = lane >> 2, cth = lane & 3;
    int mi, nt; bool act;
    if (M == 64) { mi = w & 3; nt = w >> 2; act = true; }
    else         { mi = w & 1; nt = w >> 1; act = (w < 8); }
    if (!act) return;
    const u32 ab = hbase + 4u * (u32)(mi * 16 * SU + ldm_row(lane) * SU + ldm_col(lane));
    float acc[4] = {0.0f, 0.0f, 0.0f, 0.0f};
#pragma unroll
    for (int ks = 0; ks < 8; ks++) {
        u32 a[4];
        ldmA(a, ab + 4u * (u32)(ks * 8));
        u64 b = bt[(ks * 4 + nt) * 32 + lane];
        mma16(acc, a, (u32)b, (u32)(b >> 32));
    }
    int c0 = nt * 8 + 2 * cth;
    float b0v = bl2[c0], b1v = bl2[c0 + 1];
    float vv[4] = { acc[0] + b0v, acc[1] + b1v, acc[2] + b0v, acc[3] + b1v };
#pragma unroll
    for (int q = 0; q < 4; q++) vv[q] = (vv[q] >= 0.0f) ? vv[q] : al * vv[q];
    int rows[2] = { mi * 16 + r, mi * 16 + r + 8 };
#pragma unroll
    for (int h = 0; h < 2; h++) {
        int row = rows[h];
#pragma unroll
        for (int e = 0; e < 2; e++) {
            int c = c0 + e;
            float v = vv[h * 2 + e];
            if (FINAL) {
                int be = b0 + (row >> 1);
                if (be < nbat) out[(size_t)be * 64 + (row & 1) * 32 + c] = v;
            } else {
                if (c < 12) S12[row * 12 + c] = v;
            }
        }
    }
}

// ---------- full combine() pipeline (WT pre-loaded with Wc2 by caller) ----------
template<int M, bool FINAL>
DEVINL void pipeline(float* sm, int tid,
                     const float* bc1, float ac, const float* bc2,
                     const float* bp1, float ap, const float* bp2,
                     const float* bl1, const float* bl2, float al,
                     float* out, int b0, int nbat)
{
    u32* Uu  = (u32*)(sm + SM_UU);
    u32* CHu = (u32*)(sm + SM_CH);
    u32* Hu  = (u32*)(sm + SM_HU);
    u64* WTd  = (u64*)(sm + SM_WT);    // 8192 u64; lower half also Q1/Q3 buffer
    u64* WTBd = (u64*)(sm + SM_WTB);   // 4096 u64 (Q0/Q2 buffer)
    u64* WFd  = (u64*)(sm + SM_WF);
    float* S12 = sm + SM_S12;
    const u64* G = g_packed;
    const u32 xb = s2u(sm + SM_XH), yb = s2u(sm + SM_YH);
    const u32 ub = s2u(Uu), cb = s2u(CHu), hb = s2u(Hu);

    // child: WF <- Wc1 frags (Wc2 already streaming into WT from caller/prev stage)
    for (int s = tid; s < 512; s += NTH) cpa16(WFd + s * 2, G + OWC1 + s * 2);
    cpa_commit();
    cpa_wait0();           // WF + pending WT done
    __syncthreads();
    layer1m<M, 2, SXU>(xb, WFd, bc1, ac, Uu, tid);
    __syncthreads();
    layer2<M>(ub, WTd, bc2, CHu, 0, tid);
    __syncthreads();

    // parent: WF <- Wp1, WT <- Wp2
    for (int s = tid; s < 256; s += NTH) cpa16(WFd + s * 2, G + OWP1 + s * 2);
    cpa_commit();
    for (int s = tid; s < 4096; s += NTH) cpa16(WTd + s * 2, G + OP2 + s * 2);
    cpa_commit();
    cpa_wait1();           // WF done, WT streaming
    __syncthreads();
    layer1m<M, 1, SYU>(yb, WFd, bp1, ap, Uu, tid);
    cpa_wait0();           // Wp2 done
    __syncthreads();
    // prefetch Wl1 Q0 -> WTB and Wl2 -> WF behind B2
    for (int s = tid; s < 2048; s += NTH) cpa16(WTBd + s * 2, G + OL1 + s * 2);
    cpa_commit();
    for (int s = tid; s < 512; s += NTH) cpa16(WFd + s * 2, G + OWL2 + s * 2);
    cpa_commit();
    layer2<M>(ub, WTd, bp2, CHu, 128, tid);
    __syncthreads();       // Wp2 readers done
    // Q1 -> WT low half behind pass0
    for (int s = tid; s < 2048; s += NTH) cpa16(WTd + s * 2, G + OL1 + 4096 + s * 2);
    cpa_commit();
    cpa_wait1();           // Q0 + Wl2 done, Q1 pending
    __syncthreads();

    float acc[2][2][4];
#pragma unroll
    for (int a = 0; a < 2; a++)
#pragma unroll
        for (int b = 0; b < 2; b++)
#pragma unroll
            for (int q = 0; q < 4; q++) acc[a][b][q] = 0.0f;

    layer3_q<M>(cb, WTBd, acc, 0, tid);
    __syncthreads();       // WTB readers done
    for (int s = tid; s < 2048; s += NTH) cpa16(WTBd + s * 2, G + OL1 + 8192 + s * 2);
    cpa_commit();          // Q2
    cpa_wait1();           // Q1 done
    __syncthreads();
    layer3_q<M>(cb, WTd, acc, 1, tid);
    __syncthreads();       // WT-low readers done
    for (int s = tid; s < 2048; s += NTH) cpa16(WTd + s * 2, G + OL1 + 12288 + s * 2);
    cpa_commit();          // Q3
    cpa_wait1();           // Q2 done
    __syncthreads();
    layer3_q<M>(cb, WTBd, acc, 2, tid);
    __syncthreads();
    cpa_wait0();           // Q3 done
    __syncthreads();
    layer3_q<M>(cb, WTd, acc, 3, tid);
    epi_l3<M>(acc, bl1, Hu, tid);
    __syncthreads();       // Hu ready; WT readers done
    if (!FINAL) {          // prefetch next stage's Wc2 behind layer4 + staging
        for (int s = tid; s < 4096; s += NTH) cpa16(WTd + s * 2, G + OC2 + s * 2);
        cpa_commit();
    }
    layer4m<M, FINAL>(hb, WFd, bl2, al, S12, out, b0, nbat, tid);
}

__global__ void __launch_bounds__(NTH, 1)
rvnn_kernel(const float* __restrict__ level1, const float* __restrict__ level2,
            const float* __restrict__ level3,
            const float* __restrict__ bc1, const float* __restrict__ ac,
            const float* __restrict__ bc2,
            const float* __restrict__ bp1, const float* __restrict__ ap,
            const float* __restrict__ bp2,
            const float* __restrict__ bl1,
            const float* __restrict__ bl2, const float* __restrict__ al,
            float* __restrict__ out, int nbat)
{
    extern __shared__ float sm[];
    const int tid = threadIdx.x;
    const int b0 = blockIdx.x * BB;
    const float acv = *ac, apv = *ap, alv = *al;

    u32* Xu  = (u32*)(sm + SM_XH);
    u32* Yu  = (u32*)(sm + SM_YH);
    u64* WTd = (u64*)(sm + SM_WT);
    float* S12 = sm + SM_S12;

    // kick off first Wc2 image load (overlaps input staging)
    for (int s = tid; s < 4096; s += NTH) cpa16(WTd + s * 2, g_packed + OC2 + s * 2);
    cpa_commit();

    // ---- stage 1 staging: Xh 64x16 pairs (pair-reversed level3), Yh 64x8 (level2) ----
    {
        const float* src = level3 + (size_t)b0 * 96;
        int lim = (nbat - b0 < BB ? nbat - b0 : BB) * 96;
        for (int i = tid; i < 64 * 16; i += NTH) {
            int row = i >> 4, j = i & 15;
            u32 val = 0;
            if (j < 12) {
                int be = row >> 2, p = row & 3;
                int cs, k;
                if (j < 6) { cs = 2 * p + 1; k = 2 * j; }
                else       { cs = 2 * p;     k = 2 * j - 12; }
                int gi = be * 96 + cs * 12 + k;
                float v0 = (gi < lim) ? sanf(src[gi]) : 0.0f;
                float v1 = (gi + 1 < lim) ? sanf(src[gi + 1]) : 0.0f;
                val = pkh2(v0, v1);
            }
            Xu[row * SXU + j] = val;
        }
    }
    {
        const float* src = level2 + (size_t)b0 * 48;
        int lim = (nbat - b0 < BB ? nbat - b0 : BB) * 48;
        for (int i = tid; i < 64 * 8; i += NTH) {
            int row = i >> 3, j = i & 7;
            u32 val = 0;
            if (j < 6) {
                int be = row >> 2, p = row & 3;
                int gi = be * 48 + p * 12 + 2 * j;
                float v0 = (gi < lim) ? sanf(src[gi]) : 0.0f;
                float v1 = (gi + 1 < lim) ? sanf(src[gi + 1]) : 0.0f;
                val = pkh2(v0, v1);
            }
            Yu[row * SYU + j] = val;
        }
    }
    __syncthreads();

    pipeline<64, false>(sm, tid, bc1, acv, bc2, bp1, apv, bp2, bl1, bl2, alv,
                        out, b0, nbat);
    __syncthreads();

    // ---- stage 2 staging: Xh 32x16 from S12 (pair-reversed), Yh 32x8 (level1) ----
    for (int i = tid; i < 32 * 16; i += NTH) {
        int row = i >> 4, j = i & 15;
        u32 val = 0;
        if (j < 12) {
            int be = row >> 1, p = row & 1;
            int jj, k;
            if (j < 6) { jj = 2 * p + 1; k = 2 * j; }
            else       { jj = 2 * p;     k = 2 * j - 12; }
            float v0 = sanf(S12[(be * 4 + jj) * 12 + k]);
            float v1 = sanf(S12[(be * 4 + jj) * 12 + k + 1]);
            val = pkh2(v0, v1);
        }
        Xu[row * SXU + j] = val;
    }
    {
        const float* src = level1 + (size_t)b0 * 24;
        int lim = (nbat - b0 < BB ? nbat - b0 : BB) * 24;
        for (int i = tid; i < 32 * 8; i += NTH) {
            int row = i >> 3, j = i & 7;
            u32 val = 0;
            if (j < 6) {
                int be = row >> 1, p = row & 1;
                int gi = be * 24 + p * 12 + 2 * j;
                float v0 = (gi < lim) ? sanf(src[gi]) : 0.0f;
                float v1 = (gi + 1 < lim) ? sanf(src[gi + 1]) : 0.0f;
                val = pkh2(v0, v1);
            }
            Yu[row * SYU + j] = val;
        }
    }
    __syncthreads();

    pipeline<32, true>(sm, tid, bc1, acv, bc2, bp1, apv, bp2, bl1, bl2, alv,
                       out, b0, nbat);
}

extern "C" void kernel_launch(void* const* d_in, const int* in_sizes, int n_in,
                              void* d_out, int out_size) {
    const float* level1 = (const float*)d_in[0];
    const float* level2 = (const float*)d_in[1];
    const float* level3 = (const float*)d_in[2];
    const float* Wc1 = (const float*)d_in[3];
    const float* bc1 = (const float*)d_in[4];
    const float* ac  = (const float*)d_in[5];
    const float* Wc2 = (const float*)d_in[6];
    const float* bc2 = (const float*)d_in[7];
    const float* Wp1 = (const float*)d_in[8];
    const float* bp1 = (const float*)d_in[9];
    const float* ap  = (const float*)d_in[10];
    const float* Wp2 = (const float*)d_in[11];
    const float* bp2 = (const float*)d_in[12];
    const float* Wl1 = (const float*)d_in[13];
    const float* bl1 = (const float*)d_in[14];
    const float* Wl2 = (const float*)d_in[15];
    const float* bl2 = (const float*)d_in[16];
    const float* al  = (const float*)d_in[17];
    float* out = (float*)d_out;

    int nbat = in_sizes[0] / 24;
    int grid = (nbat + BB - 1) / BB;
    size_t smem = (size_t)SM_TOT * sizeof(float);  // 219136 B

    prepack_kernel<<<(NP + 255) / 256, 256>>>(Wc2, Wp2, Wl1, Wc1, Wp1, Wl2);

    cudaFuncSetAttribute(rvnn_kernel, cudaFuncAttributeMaxDynamicSharedMemorySize, (int)smem);
    rvnn_kernel<<<grid, NTH, smem>>>(level1, level2, level3, bc1, ac, bc2,
                                     bp1, ap, bp2, bl1, bl2, al, out, nbat);
}